// round 8
// baseline (speedup 1.0000x reference)
#include <cuda_runtime.h>
#include <cuda_fp16.h>
#include <cstdint>

#define HW  4096
#define DIN 256
#define DK  64
#define DV  256
#define NB  4

// Scratch (device globals: no allocation allowed)
__device__ float    g_Q[NB * DK * HW];            // raw Q [b][k][hw] fp32
__device__ uint32_t g_K2H[NB * (DK/2) * HW];      // K hi, fp16x2 packed along dk
__device__ uint32_t g_K2L[NB * (DK/2) * HW];      // K lo residual
__device__ uint32_t g_V2[NB * DV * (HW/2)];       // V fp16x2 packed along hw

#define INVLN2 1.4426950408889634f

// ---------------------------------------------------------------------------
// helpers
// ---------------------------------------------------------------------------
__device__ __forceinline__ uint32_t h2u(__half2 h) {
    return *reinterpret_cast<uint32_t*>(&h);
}
__device__ __forceinline__ uint32_t packh2(float lo_elem, float hi_elem) {
    __half2 h = __floats2half2_rn(lo_elem, hi_elem);  // .x = low half
    return h2u(h);
}
__device__ __forceinline__ float ex2f(float x) {
    float r; asm("ex2.approx.f32 %0, %1;" : "=f"(r) : "f"(x)); return r;
}
__device__ __forceinline__ uint32_t smem_u32(const void* p) {
    uint32_t r;
    asm("{ .reg .u64 t; cvta.to.shared.u64 t, %1; cvt.u32.u64 %0, t; }"
        : "=r"(r) : "l"(p));
    return r;
}
__device__ __forceinline__ void cpa16(uint32_t dst, const uint32_t* src) {
    asm volatile("cp.async.cg.shared.global [%0], [%1], 16;"
                 :: "r"(dst), "l"(__cvta_generic_to_global(src)) : "memory");
}
#define CP_COMMIT() asm volatile("cp.async.commit_group;" ::: "memory")
#define CP_WAIT(n)  asm volatile("cp.async.wait_group %0;" :: "n"(n) : "memory")
#define NBAR(id)    asm volatile("bar.sync %0, 128;" :: "r"(id) : "memory")

__device__ __forceinline__ void mma_f16(float c[4], const uint32_t a[4],
                                        uint32_t b0, uint32_t b1) {
    asm volatile(
        "mma.sync.aligned.m16n8k16.row.col.f32.f16.f16.f32 "
        "{%0,%1,%2,%3}, {%4,%5,%6,%7}, {%8,%9}, {%0,%1,%2,%3};"
        : "+f"(c[0]), "+f"(c[1]), "+f"(c[2]), "+f"(c[3])
        : "r"(a[0]), "r"(a[1]), "r"(a[2]), "r"(a[3]), "r"(b0), "r"(b1));
}

// ---------------------------------------------------------------------------
// Projection GEMM: Out[b][r][p] = sum_c W[r][c] * X[b][c][p]
// sel 0: raw fp32 -> g_Q
// sel 1: fp16 hi/lo split, packed along dk -> g_K2H / g_K2L
// sel 2: fp16, packed along hw -> g_V2
// ---------------------------------------------------------------------------
__global__ __launch_bounds__(256) void proj_kernel(
    const float* __restrict__ W, const float* __restrict__ X, int sel)
{
    __shared__ __align__(16) float Wt[16][68];
    __shared__ __align__(16) float Xt[16][64];

    const int t  = threadIdx.x;
    const int b  = blockIdx.z;
    const int r0 = blockIdx.y * 64;
    const int p0 = blockIdx.x * 64;

    const float* Xb = X + (size_t)b * DIN * HW;

    const int tr = t >> 4;
    const int tc = t & 15;

    float acc[4][4];
#pragma unroll
    for (int i = 0; i < 4; i++)
#pragma unroll
        for (int j = 0; j < 4; j++) acc[i][j] = 0.f;

    for (int ck = 0; ck < DIN; ck += 16) {
        const int wc = t & 15;
        const int wr = t >> 4;
#pragma unroll
        for (int i = 0; i < 4; i++)
            Wt[wc][wr + 16 * i] = W[(r0 + wr + 16 * i) * DIN + ck + wc];
        const int xp = t & 63;
        const int xc = t >> 6;
#pragma unroll
        for (int i = 0; i < 4; i++)
            Xt[xc + 4 * i][xp] = Xb[(size_t)(ck + xc + 4 * i) * HW + p0 + xp];
        __syncthreads();

#pragma unroll
        for (int c = 0; c < 16; c++) {
            float4 w4 = *(const float4*)&Wt[c][tr * 4];
            float4 x4 = *(const float4*)&Xt[c][tc * 4];
            float wa[4] = {w4.x, w4.y, w4.z, w4.w};
            float xa[4] = {x4.x, x4.y, x4.z, x4.w};
#pragma unroll
            for (int i = 0; i < 4; i++)
#pragma unroll
                for (int j = 0; j < 4; j++) acc[i][j] += wa[i] * xa[j];
        }
        __syncthreads();
    }

    if (sel == 0) {
        float* Ob = g_Q + (size_t)b * DK * HW;
#pragma unroll
        for (int i = 0; i < 4; i++) {
            float4 o = make_float4(acc[i][0], acc[i][1], acc[i][2], acc[i][3]);
            *(float4*)&Ob[(size_t)(r0 + tr * 4 + i) * HW + p0 + tc * 4] = o;
        }
    } else if (sel == 1) {
        uint32_t* KH = g_K2H + (size_t)b * (DK / 2) * HW;
        uint32_t* KL = g_K2L + (size_t)b * (DK / 2) * HW;
#pragma unroll
        for (int pr = 0; pr < 2; pr++) {
            const int kp = tr * 2 + pr;
#pragma unroll
            for (int j = 0; j < 4; j++) {
                float v0 = acc[pr * 2 + 0][j];
                float v1 = acc[pr * 2 + 1][j];
                __half hh0 = __float2half_rn(v0);
                __half hh1 = __float2half_rn(v1);
                float l0 = v0 - __half2float(hh0);
                float l1 = v1 - __half2float(hh1);
                size_t off = (size_t)kp * HW + p0 + tc * 4 + j;
                KH[off] = h2u(__halves2half2(hh0, hh1));
                KL[off] = packh2(l0, l1);
            }
        }
    } else {
        uint32_t* Vg = g_V2 + (size_t)b * DV * (HW / 2);
#pragma unroll
        for (int i = 0; i < 4; i++) {
            const size_t base = (size_t)(r0 + tr * 4 + i) * (HW / 2) + p0 / 2 + tc * 2;
            Vg[base]     = packh2(acc[i][0], acc[i][1]);
            Vg[base + 1] = packh2(acc[i][2], acc[i][3]);
        }
    }
}

// ---------------------------------------------------------------------------
// fp16 flash attention, log2-domain softmax, double-buffered cp.async K/V,
// row-group named barriers (phase skew across groups).
// CTA = (batch, 128-query tile), 512 threads, 64-key tiles.
// Per tile: CP_WAIT; fullbar; S(3-term fp16); nbar(max); exp2/P; nbar; AV;
//           fullbar; issue group kt+2.
// ---------------------------------------------------------------------------
#define QS2 36
#define KS2 68
#define VS2 36
#define PS2 36
#define WOFF_QH  0
#define WOFF_QL  4608
#define WOFF_KH0 9216
#define WOFF_KH1 11392
#define WOFF_KL0 13568
#define WOFF_KL1 15744
#define WOFF_V0  17920
#define WOFF_V1  27136
#define WOFF_P   36352
#define SMEM_WORDS 40960    // 163840 bytes

__global__ __launch_bounds__(512, 1) void attn_mma_kernel(float* __restrict__ Out)
{
    extern __shared__ uint32_t sm[];
    __shared__ __align__(16) float s_max[128][4];
    __shared__ float s_part[128][4];
    __shared__ float s_inv[128];

    uint32_t* QH = sm + WOFF_QH;
    uint32_t* QL = sm + WOFF_QL;
    uint32_t* KHb[2] = { sm + WOFF_KH0, sm + WOFF_KH1 };
    uint32_t* KLb[2] = { sm + WOFF_KL0, sm + WOFF_KL1 };
    uint32_t* VVb[2] = { sm + WOFF_V0,  sm + WOFF_V1 };
    uint32_t* PP = sm + WOFF_P;

    const uint32_t SB = smem_u32(sm);
    const uint32_t kh_dst[2] = { SB + WOFF_KH0 * 4, SB + WOFF_KH1 * 4 };
    const uint32_t kl_dst[2] = { SB + WOFF_KL0 * 4, SB + WOFF_KL1 * 4 };
    const uint32_t vv_dst[2] = { SB + WOFF_V0 * 4,  SB + WOFF_V1 * 4 };

    const int t    = threadIdx.x;
    const int w    = t >> 5;
    const int lane = t & 31;
    const int mg   = w >> 2;          // 0..3 : 32-row group
    const int ng   = w & 3;           // 0..3 : 16-col group (S) / 64-v group (AV)
    const int m0   = mg * 32;
    const int lr   = lane >> 2;       // groupID 0..7
    const int lc   = lane & 3;        // threadID-in-group 0..3
    const int b    = blockIdx.y;
    const int p0   = blockIdx.x * 128;
    const int barid = 1 + mg;

    const float*    Qb  = g_Q   + (size_t)b * DK * HW;
    const uint32_t* KHg = g_K2H + (size_t)b * (DK / 2) * HW;
    const uint32_t* KLg = g_K2L + (size_t)b * (DK / 2) * HW;
    const uint32_t* Vg  = g_V2  + (size_t)b * DV * (HW / 2);

    // cp.async coordinates
    const int kkp = t >> 4;            // K: 32 kp rows x 16 chunks = 1/thread
    const int kc4 = t & 15;

    // one combined group (KH + KL + V) per tile, into buffer p
#define ISSUE_GROUP(kt_, p_) do {                                             \
        const int n0_  = (kt_) * 64;                                          \
        const int nw0_ = (kt_) * 32;                                          \
        uint32_t doff_ = (uint32_t)(kkp * KS2 + kc4 * 4) * 4;                 \
        cpa16(kh_dst[p_] + doff_, KHg + (size_t)kkp * HW + n0_ + kc4 * 4);    \
        cpa16(kl_dst[p_] + doff_, KLg + (size_t)kkp * HW + n0_ + kc4 * 4);    \
        _Pragma("unroll")                                                     \
        for (int j_ = 0; j_ < 4; j_++) {                                      \
            int id_ = t + j_ * 512;                                           \
            int row_ = id_ >> 3, c4_ = id_ & 7;                               \
            cpa16(vv_dst[p_] + (uint32_t)(row_ * VS2 + c4_ * 4) * 4,          \
                  Vg + (size_t)row_ * (HW / 2) + nw0_ + c4_ * 4);             \
        }                                                                     \
        CP_COMMIT();                                                          \
    } while (0)

    // ---- prologue: issue groups 0 and 1 ----
    ISSUE_GROUP(0, 0);
    ISSUE_GROUP(1, 1);

    // ---- load + split Q tile (scaled by 1/ln2, overlaps inflight copies) ----
#pragma unroll
    for (int i = 0; i < 8; i++) {
        int idx = t + i * 512;
        int mm = idx & 127, kp = idx >> 7;
        float q0 = Qb[(size_t)(2 * kp) * HW + p0 + mm] * INVLN2;
        float q1 = Qb[(size_t)(2 * kp + 1) * HW + p0 + mm] * INVLN2;
        __half h0 = __float2half_rn(q0);
        __half h1 = __float2half_rn(q1);
        QH[mm * QS2 + kp] = h2u(__halves2half2(h0, h1));
        QL[mm * QS2 + kp] = packh2(q0 - __half2float(h0), q1 - __half2float(h1));
    }

    float o[2][8][4];
#pragma unroll
    for (int mt = 0; mt < 2; mt++)
#pragma unroll
        for (int vt = 0; vt < 8; vt++)
#pragma unroll
            for (int j = 0; j < 4; j++) o[mt][vt][j] = 0.f;
    float rs[4]   = {0.f, 0.f, 0.f, 0.f};
    float runm[4] = {-1e30f, -1e30f, -1e30f, -1e30f};

    for (int kt = 0; kt < 64; kt++) {
        const int p = kt & 1;
        const uint32_t* KH = KHb[p];
        const uint32_t* KL = KLb[p];
        const uint32_t* VV = VVb[p];

        // ---- group kt complete + visible CTA-wide ----
        if (kt == 63) { CP_WAIT(0); } else { CP_WAIT(1); }
        __syncthreads();

        // ---- S = Qh*Kh + Qh*Kl + Ql*Kh (fp16 split, fp32 accum) ----
        float c[2][2][4];
#pragma unroll
        for (int mt = 0; mt < 2; mt++)
#pragma unroll
            for (int nt = 0; nt < 2; nt++)
#pragma unroll
                for (int j = 0; j < 4; j++) c[mt][nt][j] = 0.f;

#pragma unroll
        for (int it = 0; it < 4; it++) {
            const int kw0 = it * 8 + lc;
            uint32_t ah[2][4], al[2][4];
#pragma unroll
            for (int mt = 0; mt < 2; mt++) {
                const int ar = m0 + mt * 16 + lr;
                ah[mt][0] = QH[ar * QS2 + kw0];
                ah[mt][1] = QH[(ar + 8) * QS2 + kw0];
                ah[mt][2] = QH[ar * QS2 + kw0 + 4];
                ah[mt][3] = QH[(ar + 8) * QS2 + kw0 + 4];
                al[mt][0] = QL[ar * QS2 + kw0];
                al[mt][1] = QL[(ar + 8) * QS2 + kw0];
                al[mt][2] = QL[ar * QS2 + kw0 + 4];
                al[mt][3] = QL[(ar + 8) * QS2 + kw0 + 4];
            }
#pragma unroll
            for (int nt = 0; nt < 2; nt++) {
                const int bc = ng * 16 + nt * 8 + lr;
                uint32_t bh0 = KH[kw0 * KS2 + bc];
                uint32_t bh1 = KH[(kw0 + 4) * KS2 + bc];
                uint32_t bl0 = KL[kw0 * KS2 + bc];
                uint32_t bl1 = KL[(kw0 + 4) * KS2 + bc];
#pragma unroll
                for (int mt = 0; mt < 2; mt++) {
                    mma_f16(c[mt][nt], ah[mt], bh0, bh1);
                    mma_f16(c[mt][nt], ah[mt], bl0, bl1);
                    mma_f16(c[mt][nt], al[mt], bh0, bh1);
                }
            }
        }

        // ---- warp-partial row max -> smem (row-group scope) ----
#pragma unroll
        for (int mt = 0; mt < 2; mt++) {
            float mx0 = fmaxf(fmaxf(c[mt][0][0], c[mt][0][1]),
                              fmaxf(c[mt][1][0], c[mt][1][1]));
            float mx1 = fmaxf(fmaxf(c[mt][0][2], c[mt][0][3]),
                              fmaxf(c[mt][1][2], c[mt][1][3]));
            mx0 = fmaxf(mx0, __shfl_xor_sync(0xffffffffu, mx0, 1));
            mx0 = fmaxf(mx0, __shfl_xor_sync(0xffffffffu, mx0, 2));
            mx1 = fmaxf(mx1, __shfl_xor_sync(0xffffffffu, mx1, 1));
            mx1 = fmaxf(mx1, __shfl_xor_sync(0xffffffffu, mx1, 2));
            if (lc == 0) {
                s_max[m0 + mt * 16 + lr][ng]     = mx0;
                s_max[m0 + mt * 16 + lr + 8][ng] = mx1;
            }
        }
        NBAR(barid);

        // ---- tile max, conditional online rescale (log2 domain) ----
        float nm[4], corr[4];
#pragma unroll
        for (int s = 0; s < 4; s++) {
            const int row = m0 + (s >> 1) * 16 + (s & 1) * 8 + lr;
            float4 mv = *(const float4*)&s_max[row][0];
            float tmax = fmaxf(fmaxf(mv.x, mv.y), fmaxf(mv.z, mv.w));
            if (tmax > runm[s]) {
                nm[s] = tmax;
                corr[s] = ex2f(runm[s] - tmax);
                rs[s] *= corr[s];
                runm[s] = tmax;
            } else {
                nm[s] = runm[s];
                corr[s] = 1.f;
            }
        }
#pragma unroll
        for (int mt = 0; mt < 2; mt++) {
            if (corr[mt * 2] != 1.f || corr[mt * 2 + 1] != 1.f) {
#pragma unroll
                for (int vt = 0; vt < 8; vt++) {
                    o[mt][vt][0] *= corr[mt * 2];
                    o[mt][vt][1] *= corr[mt * 2];
                    o[mt][vt][2] *= corr[mt * 2 + 1];
                    o[mt][vt][3] *= corr[mt * 2 + 1];
                }
            }
        }

        // ---- exp2, P -> SMEM fp16x2, rowsums ----
#pragma unroll
        for (int mt = 0; mt < 2; mt++) {
            const int row = m0 + mt * 16 + lr;
            const float nm0 = nm[mt * 2], nm1 = nm[mt * 2 + 1];
#pragma unroll
            for (int nt = 0; nt < 2; nt++) {
                const int np = ng * 8 + nt * 4 + lc;
                float e0 = ex2f(c[mt][nt][0] - nm0);
                float e1 = ex2f(c[mt][nt][1] - nm0);
                float e2 = ex2f(c[mt][nt][2] - nm1);
                float e3 = ex2f(c[mt][nt][3] - nm1);
                PP[row * PS2 + np]       = packh2(e0, e1);
                PP[(row + 8) * PS2 + np] = packh2(e2, e3);
                rs[mt * 2 + 0] += e0 + e1;
                rs[mt * 2 + 1] += e2 + e3;
            }
        }
        NBAR(barid);   // P ready within row group

        // ---- O += P * V^T ----
#pragma unroll
        for (int it = 0; it < 4; it++) {
            const int kw0 = it * 8 + lc;
            uint32_t a[2][4];
#pragma unroll
            for (int mt = 0; mt < 2; mt++) {
                const int ar = m0 + mt * 16 + lr;
                a[mt][0] = PP[ar * PS2 + kw0];
                a[mt][1] = PP[(ar + 8) * PS2 + kw0];
                a[mt][2] = PP[ar * PS2 + kw0 + 4];
                a[mt][3] = PP[(ar + 8) * PS2 + kw0 + 4];
            }
#pragma unroll
            for (int vt = 0; vt < 8; vt++) {
                const int vcol = ng * 64 + vt * 8 + lr;
                uint32_t b0 = VV[vcol * VS2 + kw0];
                uint32_t b1 = VV[vcol * VS2 + kw0 + 4];
                mma_f16(o[0][vt], a[0], b0, b1);
                mma_f16(o[1][vt], a[1], b0, b1);
            }
        }

        // ---- tile fully consumed; buffer p free -> issue group kt+2 ----
        __syncthreads();
        if (kt < 62) ISSUE_GROUP(kt + 2, p);
    }

    // ---- rowsum reduction across lanes and ng groups ----
#pragma unroll
    for (int i = 0; i < 4; i++) {
        rs[i] += __shfl_xor_sync(0xffffffffu, rs[i], 1);
        rs[i] += __shfl_xor_sync(0xffffffffu, rs[i], 2);
    }
    if (lc == 0) {
#pragma unroll
        for (int i = 0; i < 4; i++) {
            int row = m0 + (i >> 1) * 16 + (i & 1) * 8 + lr;
            s_part[row][ng] = rs[i];
        }
    }
    __syncthreads();
    if (t < 128)
        s_inv[t] = 1.0f / (s_part[t][0] + s_part[t][1] + s_part[t][2] + s_part[t][3]);
    __syncthreads();

    // ---- normalize + store ----
    float* Ob = Out + (size_t)b * DV * HW;
#pragma unroll
    for (int mt = 0; mt < 2; mt++) {
        const int r = m0 + mt * 16 + lr;
        const float inv0 = s_inv[r];
        const float inv1 = s_inv[r + 8];
#pragma unroll
        for (int vt = 0; vt < 8; vt++) {
            const int v = ng * 64 + vt * 8 + 2 * lc;
            Ob[(size_t)v * HW + p0 + r]           = o[mt][vt][0] * inv0;
            Ob[(size_t)(v + 1) * HW + p0 + r]     = o[mt][vt][1] * inv0;
            Ob[(size_t)v * HW + p0 + r + 8]       = o[mt][vt][2] * inv1;
            Ob[(size_t)(v + 1) * HW + p0 + r + 8] = o[mt][vt][3] * inv1;
        }
    }
}

// ---------------------------------------------------------------------------
extern "C" void kernel_launch(void* const* d_in, const int* in_sizes, int n_in,
                              void* d_out, int out_size)
{
    const float* x  = (const float*)d_in[0];
    const float* qw = (const float*)d_in[1];
    const float* kw = (const float*)d_in[2];
    const float* vw = (const float*)d_in[3];
    float* out = (float*)d_out;

    proj_kernel<<<dim3(64, 1, NB), 256>>>(qw, x, 0);
    proj_kernel<<<dim3(64, 1, NB), 256>>>(kw, x, 1);
    proj_kernel<<<dim3(64, 4, NB), 256>>>(vw, x, 2);

    const size_t smem_bytes = (size_t)SMEM_WORDS * 4;
    cudaFuncSetAttribute(attn_mma_kernel,
                         cudaFuncAttributeMaxDynamicSharedMemorySize,
                         (int)smem_bytes);
    attn_mma_kernel<<<dim3(32, NB), 512, smem_bytes>>>(out);
}

// round 9
// speedup vs baseline: 1.1448x; 1.1448x over previous
#include <cuda_runtime.h>
#include <cuda_fp16.h>
#include <cstdint>

#define HW  4096
#define DIN 256
#define DK  64
#define DV  256
#define NB  4

// Scratch (device globals: no allocation allowed)
__device__ float    g_Q[NB * DK * HW];            // raw Q [b][k][hw] fp32
__device__ uint32_t g_K2H[NB * (DK/2) * HW];      // K hi, fp16x2 packed along dk
__device__ uint32_t g_K2L[NB * (DK/2) * HW];      // K lo residual
__device__ uint32_t g_V2[NB * DV * (HW/2)];       // V fp16x2 packed along hw

#define INVLN2 1.4426950408889634f

// ---------------------------------------------------------------------------
// helpers
// ---------------------------------------------------------------------------
__device__ __forceinline__ uint32_t h2u(__half2 h) {
    return *reinterpret_cast<uint32_t*>(&h);
}
__device__ __forceinline__ uint32_t packh2(float lo_elem, float hi_elem) {
    __half2 h = __floats2half2_rn(lo_elem, hi_elem);  // .x = low half
    return h2u(h);
}
__device__ __forceinline__ float ex2f(float x) {
    float r; asm("ex2.approx.f32 %0, %1;" : "=f"(r) : "f"(x)); return r;
}
__device__ __forceinline__ uint32_t smem_u32(const void* p) {
    uint32_t r;
    asm("{ .reg .u64 t; cvta.to.shared.u64 t, %1; cvt.u32.u64 %0, t; }"
        : "=r"(r) : "l"(p));
    return r;
}
__device__ __forceinline__ void cpa16(uint32_t dst, const uint32_t* src) {
    asm volatile("cp.async.cg.shared.global [%0], [%1], 16;"
                 :: "r"(dst), "l"(__cvta_generic_to_global(src)) : "memory");
}
#define CP_COMMIT() asm volatile("cp.async.commit_group;" ::: "memory")
#define CP_WAIT(n)  asm volatile("cp.async.wait_group %0;" :: "n"(n) : "memory")

__device__ __forceinline__ void mma_f16(float c[4], const uint32_t a[4],
                                        uint32_t b0, uint32_t b1) {
    asm volatile(
        "mma.sync.aligned.m16n8k16.row.col.f32.f16.f16.f32 "
        "{%0,%1,%2,%3}, {%4,%5,%6,%7}, {%8,%9}, {%0,%1,%2,%3};"
        : "+f"(c[0]), "+f"(c[1]), "+f"(c[2]), "+f"(c[3])
        : "r"(a[0]), "r"(a[1]), "r"(a[2]), "r"(a[3]), "r"(b0), "r"(b1));
}
__device__ __forceinline__ void ldsm_x4(uint32_t r[4], uint32_t addr) {
    asm volatile("ldmatrix.sync.aligned.m8n8.x4.shared.b16 {%0,%1,%2,%3}, [%4];"
        : "=r"(r[0]), "=r"(r[1]), "=r"(r[2]), "=r"(r[3]) : "r"(addr));
}
__device__ __forceinline__ void ldsm_x2(uint32_t& r0, uint32_t& r1, uint32_t addr) {
    asm volatile("ldmatrix.sync.aligned.m8n8.x2.shared.b16 {%0,%1}, [%2];"
        : "=r"(r0), "=r"(r1) : "r"(addr));
}

// ---------------------------------------------------------------------------
// Projection GEMM: Out[b][r][p] = sum_c W[r][c] * X[b][c][p]
// sel 0: raw fp32 -> g_Q
// sel 1: fp16 hi/lo split, packed along dk -> g_K2H / g_K2L
// sel 2: fp16, packed along hw -> g_V2
// ---------------------------------------------------------------------------
__global__ __launch_bounds__(256) void proj_kernel(
    const float* __restrict__ W, const float* __restrict__ X, int sel)
{
    __shared__ __align__(16) float Wt[16][68];
    __shared__ __align__(16) float Xt[16][64];

    const int t  = threadIdx.x;
    const int b  = blockIdx.z;
    const int r0 = blockIdx.y * 64;
    const int p0 = blockIdx.x * 64;

    const float* Xb = X + (size_t)b * DIN * HW;

    const int tr = t >> 4;
    const int tc = t & 15;

    float acc[4][4];
#pragma unroll
    for (int i = 0; i < 4; i++)
#pragma unroll
        for (int j = 0; j < 4; j++) acc[i][j] = 0.f;

    for (int ck = 0; ck < DIN; ck += 16) {
        const int wc = t & 15;
        const int wr = t >> 4;
#pragma unroll
        for (int i = 0; i < 4; i++)
            Wt[wc][wr + 16 * i] = W[(r0 + wr + 16 * i) * DIN + ck + wc];
        const int xp = t & 63;
        const int xc = t >> 6;
#pragma unroll
        for (int i = 0; i < 4; i++)
            Xt[xc + 4 * i][xp] = Xb[(size_t)(ck + xc + 4 * i) * HW + p0 + xp];
        __syncthreads();

#pragma unroll
        for (int c = 0; c < 16; c++) {
            float4 w4 = *(const float4*)&Wt[c][tr * 4];
            float4 x4 = *(const float4*)&Xt[c][tc * 4];
            float wa[4] = {w4.x, w4.y, w4.z, w4.w};
            float xa[4] = {x4.x, x4.y, x4.z, x4.w};
#pragma unroll
            for (int i = 0; i < 4; i++)
#pragma unroll
                for (int j = 0; j < 4; j++) acc[i][j] += wa[i] * xa[j];
        }
        __syncthreads();
    }

    if (sel == 0) {
        float* Ob = g_Q + (size_t)b * DK * HW;
#pragma unroll
        for (int i = 0; i < 4; i++) {
            float4 o = make_float4(acc[i][0], acc[i][1], acc[i][2], acc[i][3]);
            *(float4*)&Ob[(size_t)(r0 + tr * 4 + i) * HW + p0 + tc * 4] = o;
        }
    } else if (sel == 1) {
        uint32_t* KH = g_K2H + (size_t)b * (DK / 2) * HW;
        uint32_t* KL = g_K2L + (size_t)b * (DK / 2) * HW;
#pragma unroll
        for (int pr = 0; pr < 2; pr++) {
            const int kp = tr * 2 + pr;
#pragma unroll
            for (int j = 0; j < 4; j++) {
                float v0 = acc[pr * 2 + 0][j];
                float v1 = acc[pr * 2 + 1][j];
                __half hh0 = __float2half_rn(v0);
                __half hh1 = __float2half_rn(v1);
                float l0 = v0 - __half2float(hh0);
                float l1 = v1 - __half2float(hh1);
                size_t off = (size_t)kp * HW + p0 + tc * 4 + j;
                KH[off] = h2u(__halves2half2(hh0, hh1));
                KL[off] = packh2(l0, l1);
            }
        }
    } else {
        uint32_t* Vg = g_V2 + (size_t)b * DV * (HW / 2);
#pragma unroll
        for (int i = 0; i < 4; i++) {
            const size_t base = (size_t)(r0 + tr * 4 + i) * (HW / 2) + p0 / 2 + tc * 2;
            Vg[base]     = packh2(acc[i][0], acc[i][1]);
            Vg[base + 1] = packh2(acc[i][2], acc[i][3]);
        }
    }
}

// ---------------------------------------------------------------------------
// fp16 flash attention, R7 pipeline, log2-domain softmax, ldmatrix fragments.
// CTA = (batch, 128-query tile), 512 threads, 64-key tiles.
// SMEM words (fp16x2): Q2H/Q2L [m][kp] s36 (=144B rows), K2H/K2L [kp][n] s68,
//                      V2 [v][np] s36, P2 [m][np] s36.
// 144B row stride => ldmatrix conflict-free (8 rows -> word offsets 4i mod 32).
// ---------------------------------------------------------------------------
#define QS2 36
#define KS2 68
#define VS2 36
#define PS2 36
#define WOFF_QH 0
#define WOFF_QL 4608
#define WOFF_KH 9216
#define WOFF_KL 11392
#define WOFF_V  13568
#define WOFF_P  22784
#define SMEM_WORDS 27392    // 109568 bytes

__global__ __launch_bounds__(512, 1) void attn_mma_kernel(float* __restrict__ Out)
{
    extern __shared__ uint32_t sm[];
    __shared__ __align__(16) float s_max[128][4];
    __shared__ float s_part[128][4];
    __shared__ float s_inv[128];

    uint32_t* QH = sm + WOFF_QH;
    uint32_t* QL = sm + WOFF_QL;
    uint32_t* KH = sm + WOFF_KH;
    uint32_t* KL = sm + WOFF_KL;
    uint32_t* PP = sm + WOFF_P;

    const uint32_t SB     = smem_u32(sm);
    const uint32_t kh_dst = SB + WOFF_KH * 4;
    const uint32_t kl_dst = SB + WOFF_KL * 4;
    const uint32_t vv_dst = SB + WOFF_V * 4;

    const int t    = threadIdx.x;
    const int w    = t >> 5;
    const int lane = t & 31;
    const int mg   = w >> 2;          // 0..3 : 32-row group
    const int ng   = w & 3;           // 0..3 : 16-col group (S) / 64-v group (AV)
    const int m0   = mg * 32;
    const int lr   = lane >> 2;       // groupID 0..7
    const int lc   = lane & 3;        // threadID-in-group 0..3
    const int b    = blockIdx.y;
    const int p0   = blockIdx.x * 128;

    const float*    Qb  = g_Q   + (size_t)b * DK * HW;
    const uint32_t* KHg = g_K2H + (size_t)b * (DK / 2) * HW;
    const uint32_t* KLg = g_K2L + (size_t)b * (DK / 2) * HW;
    const uint32_t* Vg  = g_V2  + (size_t)b * DV * (HW / 2);

    // ldmatrix per-thread address components
    const int  lq    = (lane & 7) + ((lane >> 3) & 1) * 8;  // row within m16
    const uint32_t colb = (uint32_t)(lane >> 4) * 16;       // 0 or 16 bytes
    const uint32_t qh_lm = SB + WOFF_QH * 4 + (uint32_t)(m0 + lq) * 144 + colb;
    const uint32_t ql_lm = SB + WOFF_QL * 4 + (uint32_t)(m0 + lq) * 144 + colb;
    const uint32_t pp_lm = SB + WOFF_P  * 4 + (uint32_t)(m0 + lq) * 144 + colb;
    // V x2: matrix j = lane>>3 (lanes 0..15 used); row v = ng*64 + (lane&7)
    const uint32_t vv_lm = SB + WOFF_V * 4 +
        (uint32_t)(ng * 64 + (lane & 7)) * 144 + (uint32_t)((lane >> 3) & 1) * 16;

    // cp.async coordinates
    const int kkp = t >> 4;            // K: 32 kp rows x 16 chunks = 1/thread
    const int kc4 = t & 15;

    // ---- issue K[0] then V[0] ----
    {
        uint32_t doff = (uint32_t)(kkp * KS2 + kc4 * 4) * 4;
        cpa16(kh_dst + doff, KHg + (size_t)kkp * HW + kc4 * 4);
        cpa16(kl_dst + doff, KLg + (size_t)kkp * HW + kc4 * 4);
        CP_COMMIT();
#pragma unroll
        for (int j = 0; j < 4; j++) {
            int id = t + j * 512;
            int row = id >> 3, c4 = id & 7;
            cpa16(vv_dst + (uint32_t)(row * VS2 + c4 * 4) * 4,
                  Vg + (size_t)row * (HW / 2) + c4 * 4);
        }
        CP_COMMIT();
    }

    // ---- load + split Q tile (scaled by 1/ln2; overlaps inflight copies) ----
#pragma unroll
    for (int i = 0; i < 8; i++) {
        int idx = t + i * 512;
        int mm = idx & 127, kp = idx >> 7;
        float q0 = Qb[(size_t)(2 * kp) * HW + p0 + mm] * INVLN2;
        float q1 = Qb[(size_t)(2 * kp + 1) * HW + p0 + mm] * INVLN2;
        __half h0 = __float2half_rn(q0);
        __half h1 = __float2half_rn(q1);
        QH[mm * QS2 + kp] = h2u(__halves2half2(h0, h1));
        QL[mm * QS2 + kp] = packh2(q0 - __half2float(h0), q1 - __half2float(h1));
    }

    float o[2][8][4];
#pragma unroll
    for (int mt = 0; mt < 2; mt++)
#pragma unroll
        for (int vt = 0; vt < 8; vt++)
#pragma unroll
            for (int j = 0; j < 4; j++) o[mt][vt][j] = 0.f;
    float rs[4]   = {0.f, 0.f, 0.f, 0.f};
    float runm[4] = {-1e30f, -1e30f, -1e30f, -1e30f};

    for (int kt = 0; kt < 64; kt++) {
        // ---- wait K[kt] (V[kt] may stay in flight) ----
        CP_WAIT(1);
        __syncthreads();

        // ---- S = Qh*Kh + Qh*Kl + Ql*Kh (fp16 split, fp32 accum) ----
        float c[2][2][4];
#pragma unroll
        for (int mt = 0; mt < 2; mt++)
#pragma unroll
            for (int nt = 0; nt < 2; nt++)
#pragma unroll
                for (int j = 0; j < 4; j++) c[mt][nt][j] = 0.f;

#pragma unroll
        for (int it = 0; it < 4; it++) {
            const int kw0 = it * 8 + lc;
            uint32_t ah[2][4], al[2][4];
#pragma unroll
            for (int mt = 0; mt < 2; mt++) {
                ldsm_x4(ah[mt], qh_lm + (uint32_t)mt * 2304 + (uint32_t)it * 32);
                ldsm_x4(al[mt], ql_lm + (uint32_t)mt * 2304 + (uint32_t)it * 32);
            }
#pragma unroll
            for (int nt = 0; nt < 2; nt++) {
                const int bc = ng * 16 + nt * 8 + lr;
                uint32_t bh0 = KH[kw0 * KS2 + bc];
                uint32_t bh1 = KH[(kw0 + 4) * KS2 + bc];
                uint32_t bl0 = KL[kw0 * KS2 + bc];
                uint32_t bl1 = KL[(kw0 + 4) * KS2 + bc];
#pragma unroll
                for (int mt = 0; mt < 2; mt++) {
                    mma_f16(c[mt][nt], ah[mt], bh0, bh1);
                    mma_f16(c[mt][nt], ah[mt], bl0, bl1);
                    mma_f16(c[mt][nt], al[mt], bh0, bh1);
                }
            }
        }

        // ---- warp-partial row max -> smem ----
#pragma unroll
        for (int mt = 0; mt < 2; mt++) {
            float mx0 = fmaxf(fmaxf(c[mt][0][0], c[mt][0][1]),
                              fmaxf(c[mt][1][0], c[mt][1][1]));
            float mx1 = fmaxf(fmaxf(c[mt][0][2], c[mt][0][3]),
                              fmaxf(c[mt][1][2], c[mt][1][3]));
            mx0 = fmaxf(mx0, __shfl_xor_sync(0xffffffffu, mx0, 1));
            mx0 = fmaxf(mx0, __shfl_xor_sync(0xffffffffu, mx0, 2));
            mx1 = fmaxf(mx1, __shfl_xor_sync(0xffffffffu, mx1, 1));
            mx1 = fmaxf(mx1, __shfl_xor_sync(0xffffffffu, mx1, 2));
            if (lc == 0) {
                s_max[m0 + mt * 16 + lr][ng]     = mx0;
                s_max[m0 + mt * 16 + lr + 8][ng] = mx1;
            }
        }
        __syncthreads();   // K consumed + s_max visible

        // ---- issue K[kt+1] ----
        if (kt < 63) {
            const int n0 = (kt + 1) * 64;
            uint32_t doff = (uint32_t)(kkp * KS2 + kc4 * 4) * 4;
            cpa16(kh_dst + doff, KHg + (size_t)kkp * HW + n0 + kc4 * 4);
            cpa16(kl_dst + doff, KLg + (size_t)kkp * HW + n0 + kc4 * 4);
            CP_COMMIT();
        }

        // ---- tile max, conditional online rescale (log2 domain) ----
        float nm[4], corr[4];
#pragma unroll
        for (int s = 0; s < 4; s++) {
            const int row = m0 + (s >> 1) * 16 + (s & 1) * 8 + lr;
            float4 mv = *(const float4*)&s_max[row][0];
            float tmax = fmaxf(fmaxf(mv.x, mv.y), fmaxf(mv.z, mv.w));
            if (tmax > runm[s]) {
                nm[s] = tmax;
                corr[s] = ex2f(runm[s] - tmax);
                rs[s] *= corr[s];
                runm[s] = tmax;
            } else {
                nm[s] = runm[s];
                corr[s] = 1.f;
            }
        }
#pragma unroll
        for (int mt = 0; mt < 2; mt++) {
            if (corr[mt * 2] != 1.f || corr[mt * 2 + 1] != 1.f) {
#pragma unroll
                for (int vt = 0; vt < 8; vt++) {
                    o[mt][vt][0] *= corr[mt * 2];
                    o[mt][vt][1] *= corr[mt * 2];
                    o[mt][vt][2] *= corr[mt * 2 + 1];
                    o[mt][vt][3] *= corr[mt * 2 + 1];
                }
            }
        }

        // ---- exp2, P -> SMEM fp16x2, rowsums ----
#pragma unroll
        for (int mt = 0; mt < 2; mt++) {
            const int row = m0 + mt * 16 + lr;
            const float nm0 = nm[mt * 2], nm1 = nm[mt * 2 + 1];
#pragma unroll
            for (int nt = 0; nt < 2; nt++) {
                const int np = ng * 8 + nt * 4 + lc;
                float e0 = ex2f(c[mt][nt][0] - nm0);
                float e1 = ex2f(c[mt][nt][1] - nm0);
                float e2 = ex2f(c[mt][nt][2] - nm1);
                float e3 = ex2f(c[mt][nt][3] - nm1);
                PP[row * PS2 + np]       = packh2(e0, e1);
                PP[(row + 8) * PS2 + np] = packh2(e2, e3);
                rs[mt * 2 + 0] += e0 + e1;
                rs[mt * 2 + 1] += e2 + e3;
            }
        }

        // ---- wait V[kt] (K[kt+1] stays in flight), make V+P visible ----
        if (kt < 63) { CP_WAIT(1); } else { CP_WAIT(0); }
        __syncthreads();

        // ---- O += P * V^T (ldmatrix fragments) ----
#pragma unroll
        for (int it = 0; it < 4; it++) {
            uint32_t a[2][4];
#pragma unroll
            for (int mt = 0; mt < 2; mt++)
                ldsm_x4(a[mt], pp_lm + (uint32_t)mt * 2304 + (uint32_t)it * 32);
#pragma unroll
            for (int vt = 0; vt < 8; vt++) {
                uint32_t b0, b1;
                ldsm_x2(b0, b1, vv_lm + (uint32_t)vt * 1152 + (uint32_t)it * 32);
                mma_f16(o[0][vt], a[0], b0, b1);
                mma_f16(o[1][vt], a[1], b0, b1);
            }
        }

        // ---- V/P consumed; issue V[kt+1] ----
        __syncthreads();
        if (kt < 63) {
            const int nw0 = (kt + 1) * 32;
#pragma unroll
            for (int j = 0; j < 4; j++) {
                int id = t + j * 512;
                int row = id >> 3, c4 = id & 7;
                cpa16(vv_dst + (uint32_t)(row * VS2 + c4 * 4) * 4,
                      Vg + (size_t)row * (HW / 2) + nw0 + c4 * 4);
            }
            CP_COMMIT();
        }
    }

    // ---- rowsum reduction across lanes and ng groups ----
#pragma unroll
    for (int i = 0; i < 4; i++) {
        rs[i] += __shfl_xor_sync(0xffffffffu, rs[i], 1);
        rs[i] += __shfl_xor_sync(0xffffffffu, rs[i], 2);
    }
    if (lc == 0) {
#pragma unroll
        for (int i = 0; i < 4; i++) {
            int row = m0 + (i >> 1) * 16 + (i & 1) * 8 + lr;
            s_part[row][ng] = rs[i];
        }
    }
    __syncthreads();
    if (t < 128)
        s_inv[t] = 1.0f / (s_part[t][0] + s_part[t][1] + s_part[t][2] + s_part[t][3]);
    __syncthreads();

    // ---- normalize + store ----
    float* Ob = Out + (size_t)b * DV * HW;
#pragma unroll
    for (int mt = 0; mt < 2; mt++) {
        const int r = m0 + mt * 16 + lr;
        const float inv0 = s_inv[r];
        const float inv1 = s_inv[r + 8];
#pragma unroll
        for (int vt = 0; vt < 8; vt++) {
            const int v = ng * 64 + vt * 8 + 2 * lc;
            Ob[(size_t)v * HW + p0 + r]           = o[mt][vt][0] * inv0;
            Ob[(size_t)(v + 1) * HW + p0 + r]     = o[mt][vt][1] * inv0;
            Ob[(size_t)v * HW + p0 + r + 8]       = o[mt][vt][2] * inv1;
            Ob[(size_t)(v + 1) * HW + p0 + r + 8] = o[mt][vt][3] * inv1;
        }
    }
}

// ---------------------------------------------------------------------------
extern "C" void kernel_launch(void* const* d_in, const int* in_sizes, int n_in,
                              void* d_out, int out_size)
{
    const float* x  = (const float*)d_in[0];
    const float* qw = (const float*)d_in[1];
    const float* kw = (const float*)d_in[2];
    const float* vw = (const float*)d_in[3];
    float* out = (float*)d_out;

    proj_kernel<<<dim3(64, 1, NB), 256>>>(qw, x, 0);
    proj_kernel<<<dim3(64, 1, NB), 256>>>(kw, x, 1);
    proj_kernel<<<dim3(64, 4, NB), 256>>>(vw, x, 2);

    const size_t smem_bytes = (size_t)SMEM_WORDS * 4;
    cudaFuncSetAttribute(attn_mma_kernel,
                         cudaFuncAttributeMaxDynamicSharedMemorySize,
                         (int)smem_bytes);
    attn_mma_kernel<<<dim3(32, NB), 512, smem_bytes>>>(out);
}